// round 1
// baseline (speedup 1.0000x reference)
#include <cuda_runtime.h>
#include <math.h>

#define B_   4096
#define T_   200
#define E_   64
#define H1_  80
#define H2_  40
#define KST  201      // padded T stride: gcd(201 mod 32, 32) = gcd(9,32)=1 -> conflict-free
#define NTHR 224

// Scratch (no allocations allowed): prepared weight blocks + normalized lengths.
__device__ float g_Wq[E_ * H1_];   // W1a + W1c  (multiplies q, folded into c_b)
__device__ float g_Wk[E_ * H1_];   // W1b - W1c  (multiplies k)
__device__ float g_Wp[E_ * H1_];   // W1d        (multiplies q*k)
__device__ int   g_len[B_];

// ---------------------------------------------------------------------------
// Prep 1: fold W1 concat blocks.
// ---------------------------------------------------------------------------
__global__ void prep_w(const float* __restrict__ W1) {
    int idx = blockIdx.x * blockDim.x + threadIdx.x;
    if (idx >= E_ * H1_) return;
    int e = idx / H1_;
    int h = idx - e * H1_;
    float wa = W1[(e          ) * H1_ + h];
    float wb = W1[(E_     + e ) * H1_ + h];
    float wc = W1[(2 * E_ + e ) * H1_ + h];
    float wd = W1[(3 * E_ + e ) * H1_ + h];
    g_Wq[idx] = wa + wc;
    g_Wk[idx] = wb - wc;
    g_Wp[idx] = wd;
}

// ---------------------------------------------------------------------------
// Prep 2: normalize keys_length. The reference requests int64 from JAX; with
// x64 disabled it silently becomes int32. Detect: interpret the first 4096
// 32-bit words (in-bounds for BOTH dtypes). If int64(LE), words 1,3,5,... are
// high words == 0. 2048 random lengths all being zero is impossible.
// ---------------------------------------------------------------------------
__global__ void prep_len(const int* __restrict__ raw) {
    int tid = threadIdx.x;
    int any = 0;
    for (int i = 2 * tid + 1; i < B_; i += 2 * blockDim.x) any |= raw[i];
    int has_odd = __syncthreads_or(any);
    int is64 = (has_odd == 0);
    for (int i = tid; i < B_; i += blockDim.x) {
        int v = is64 ? raw[2 * i] : raw[i];   // guarded: 2*i only read when buffer is int64
        g_len[i] = v < 0 ? 0 : (v > T_ ? T_ : v);
    }
}

// ---------------------------------------------------------------------------
// Main fused kernel: one block per batch element, one thread per timestep.
// ---------------------------------------------------------------------------
struct __align__(16) Smem {
    float M[E_ * H1_];      // per-batch folded layer-1 weight [e][h] (16B rows)
    float W2t[H2_ * H1_];   // W2 transposed [j][h] (16B rows)
    float K[E_ * KST];      // keys transposed [e][t]
    float C[H1_];
    float B2[H2_];
    float Wd[H2_];
    float Q[E_];
    float Score[256];
};

extern __shared__ char smem_raw[];

__global__ void __launch_bounds__(NTHR, 2)
din_kernel(const float* __restrict__ query, const float* __restrict__ keys,
           const float* __restrict__ b1v,   const float* __restrict__ W2,
           const float* __restrict__ b2v,   const float* __restrict__ Wdv,
           const float* __restrict__ bdv,   float* __restrict__ out)
{
    Smem* s = (Smem*)smem_raw;
    const int tid = threadIdx.x;
    const int b   = blockIdx.x;
    const int len = g_len[b];

    // Phase 0: small vectors
    if (tid < E_) s->Q[tid] = query[b * E_ + tid];
    if (tid >= 64 && tid < 64 + H2_) {
        int j = tid - 64;
        s->B2[j] = b2v[j];
        s->Wd[j] = Wdv[j];
    }
    __syncthreads();

    // Phase 1: build M_b, c_b, W2^T; stage keys (only rows t < len)
    for (int idx = tid; idx < E_ * H1_; idx += NTHR) {
        int e = idx / H1_;
        s->M[idx] = g_Wk[idx] + s->Q[e] * g_Wp[idx];
    }
    if (tid < H1_) {
        float c = b1v[tid];
        for (int e = 0; e < E_; e++) c += s->Q[e] * g_Wq[e * H1_ + tid];
        s->C[tid] = c;
    }
    for (int idx = tid; idx < H1_ * H2_; idx += NTHR) {
        int h = idx / H2_;
        int j = idx - h * H2_;
        s->W2t[j * H1_ + h] = W2[idx];
    }
    {
        const float* kb = keys + (size_t)b * (T_ * E_);
        int ne = len * E_;
        for (int idx = tid; idx < ne; idx += NTHR) {
            int t = idx >> 6;
            int e = idx & 63;
            s->K[e * KST + t] = kb[idx];   // coalesced read, conflict-free write
        }
    }
    __syncthreads();

    // Phase 2: per-timestep MLP (thread t), masked threads skip entirely
    const int t = tid;
    float score = 0.f;
    if (t < len) {
        float acc[H1_];
        #pragma unroll
        for (int h = 0; h < H1_; h++) acc[h] = s->C[h];

        const float* kcol = &s->K[t];
        for (int e = 0; e < E_; e++) {
            float kv = kcol[e * KST];                       // stride-1 across lanes
            const float4* mrow = (const float4*)&s->M[e * H1_];
            #pragma unroll
            for (int q4 = 0; q4 < H1_ / 4; q4++) {          // LDS.128 broadcast: 4 FFMA / LDS
                float4 m = mrow[q4];
                acc[4 * q4 + 0] += kv * m.x;
                acc[4 * q4 + 1] += kv * m.y;
                acc[4 * q4 + 2] += kv * m.z;
                acc[4 * q4 + 3] += kv * m.w;
            }
        }
        #pragma unroll
        for (int h = 0; h < H1_; h++)
            acc[h] = 1.f / (1.f + __expf(-acc[h]));

        float sc = 0.f;
        for (int j = 0; j < H2_; j++) {
            const float4* wrow = (const float4*)&s->W2t[j * H1_];
            float s0 = 0.f, s1 = 0.f, s2 = 0.f, s3 = 0.f;
            #pragma unroll
            for (int q4 = 0; q4 < H1_ / 4; q4++) {
                float4 w = wrow[q4];
                s0 += acc[4 * q4 + 0] * w.x;
                s1 += acc[4 * q4 + 1] * w.y;
                s2 += acc[4 * q4 + 2] * w.z;
                s3 += acc[4 * q4 + 3] * w.w;
            }
            float hp = s->B2[j] + ((s0 + s1) + (s2 + s3));
            float h2 = 1.f / (1.f + __expf(-hp));
            sc += h2 * s->Wd[j];
        }
        score = sc + bdv[0];
    }
    s->Score[tid] = score;
    __syncthreads();

    // Phase 3: pooling out[e] = sum_{t<len} score[t] * K[t][e]
    if (tid < E_) {
        float ssum = 0.f;
        const float* krow = &s->K[tid * KST];
        for (int t2 = 0; t2 < len; t2++) ssum += s->Score[t2] * krow[t2];
        out[b * E_ + tid] = ssum;   // len==0 -> writes required 0
    }
}

// ---------------------------------------------------------------------------
extern "C" void kernel_launch(void* const* d_in, const int* in_sizes, int n_in,
                              void* d_out, int out_size) {
    const float* query = (const float*)d_in[0];
    const float* keys  = (const float*)d_in[1];
    const int*   klen  = (const int*)  d_in[2];   // width auto-detected in prep_len
    const float* W1    = (const float*)d_in[3];
    const float* b1    = (const float*)d_in[4];
    const float* W2    = (const float*)d_in[5];
    const float* b2    = (const float*)d_in[6];
    const float* Wd    = (const float*)d_in[7];
    const float* bd    = (const float*)d_in[8];
    float* out = (float*)d_out;

    // Idempotent; also set on the pre-capture correctness call.
    cudaFuncSetAttribute(din_kernel, cudaFuncAttributeMaxDynamicSharedMemorySize,
                         (int)sizeof(Smem));

    prep_w<<<(E_ * H1_ + 255) / 256, 256>>>(W1);
    prep_len<<<1, 512>>>(klen);
    din_kernel<<<B_, NTHR, sizeof(Smem)>>>(query, keys, b1, W2, b2, Wd, bd, out);
}

// round 2
// speedup vs baseline: 1.1113x; 1.1113x over previous
#include <cuda_runtime.h>
#include <math.h>

#define B_   4096
#define T_   200
#define E_   64
#define H1_  80
#define H2_  40
#define KST  201      // padded T stride: 201 mod 32 = 9, gcd(9,32)=1 -> conflict-free
#define NTHR 224
#define NWARP (NTHR/32)

// Scratch (no allocations allowed): prepared weight blocks + normalized lengths.
__device__ float g_Wq[E_ * H1_];   // W1a + W1c  (multiplies q, folded into c_b)
__device__ float g_Wk[E_ * H1_];   // W1b - W1c  (multiplies k)
__device__ float g_Wp[E_ * H1_];   // W1d        (multiplies q*k)
__device__ int   g_len[B_];

// ---------------------------------------------------------------------------
// Merged prep: blocks 0..19 fold W1 concat blocks; block 20 normalizes lengths.
// (Single prep kernel => 2 launches per kernel_launch => ncu's "-s 5 -c 1"
//  profiles din_kernel, not the prep.)
// ---------------------------------------------------------------------------
__global__ void prep(const float* __restrict__ W1, const int* __restrict__ raw) {
    if (blockIdx.x < 20) {
        int idx = blockIdx.x * 256 + threadIdx.x;
        if (idx >= E_ * H1_) return;
        int e = idx / H1_;
        int h = idx - e * H1_;
        float wa = W1[(e          ) * H1_ + h];
        float wb = W1[(E_     + e ) * H1_ + h];
        float wc = W1[(2 * E_ + e ) * H1_ + h];
        float wd = W1[(3 * E_ + e ) * H1_ + h];
        g_Wq[idx] = wa + wc;
        g_Wk[idx] = wb - wc;
        g_Wp[idx] = wd;
    } else {
        // keys_length dtype sniff: reference requests int64 but JAX without x64
        // silently gives int32. Read first 4096 32-bit words (in-bounds for
        // both). int64(LE) => all odd words (high halves) are 0.
        int tid = threadIdx.x;
        int any = 0;
        for (int i = 2 * tid + 1; i < B_; i += 2 * blockDim.x) any |= raw[i];
        int has_odd = __syncthreads_or(any);
        int is64 = (has_odd == 0);
        for (int i = tid; i < B_; i += blockDim.x) {
            int v = is64 ? raw[2 * i] : raw[i];
            g_len[i] = v < 0 ? 0 : (v > T_ ? T_ : v);
        }
    }
}

// ---------------------------------------------------------------------------
// Main fused kernel: one block per batch element, one thread per timestep.
// ---------------------------------------------------------------------------
struct __align__(16) Smem {
    float M[E_ * H1_];      // per-batch folded layer-1 weight [e][h] (16B rows)
    float W2t[H2_ * H1_];   // W2 transposed [j][h] (16B rows)
    float K[E_ * KST];      // keys transposed [e][t]
    float P[NWARP * E_];    // phase-3 per-warp partials
    float C[H1_];
    float B2[H2_];
    float Wd[H2_];
    float Q[E_];
    float Score[256];
    float bd;
};

extern __shared__ char smem_raw[];

__global__ void __launch_bounds__(NTHR, 2)
din_kernel(const float* __restrict__ query, const float* __restrict__ keys,
           const float* __restrict__ b1v,   const float* __restrict__ W2,
           const float* __restrict__ b2v,   const float* __restrict__ Wdv,
           const float* __restrict__ bdv,   float* __restrict__ out)
{
    Smem* s = (Smem*)smem_raw;
    const int tid  = threadIdx.x;
    const int wrp  = tid >> 5;
    const int lane = tid & 31;
    const int b    = blockIdx.x;
    const int len  = g_len[b];

    // Phase 0: small vectors
    if (tid < E_) s->Q[tid] = query[b * E_ + tid];
    if (tid >= 64 && tid < 64 + H2_) {
        int j = tid - 64;
        s->B2[j] = b2v[j];
        s->Wd[j] = Wdv[j];
    }
    if (tid == 104) s->bd = bdv[0];
    __syncthreads();

    // Phase 1: build M_b, c_b, W2^T; stage keys (only rows t < len)
    for (int idx = tid; idx < E_ * H1_; idx += NTHR) {
        int e = idx / H1_;
        s->M[idx] = g_Wk[idx] + s->Q[e] * g_Wp[idx];
    }
    if (tid < H1_) {
        float c = b1v[tid];
        for (int e = 0; e < E_; e++) c += s->Q[e] * g_Wq[e * H1_ + tid];
        s->C[tid] = c;
    }
    for (int idx = tid; idx < H1_ * H2_; idx += NTHR) {
        int h = idx / H2_;
        int j = idx - h * H2_;
        s->W2t[j * H1_ + h] = W2[idx];
    }
    {
        const float* kb = keys + (size_t)b * (T_ * E_);
        int ne = len * E_;
        for (int idx = tid; idx < ne; idx += NTHR) {
            int t = idx >> 6;
            int e = idx & 63;
            s->K[e * KST + t] = kb[idx];   // coalesced read, conflict-free write
        }
    }
    __syncthreads();

    // Phase 2: per-timestep MLP (thread t), masked threads skip entirely
    const int t = tid;
    float score = 0.f;
    if (t < len) {
        float acc[H1_];
        #pragma unroll
        for (int h = 0; h < H1_; h++) acc[h] = s->C[h];

        const float* kcol = &s->K[t];
        #pragma unroll 2
        for (int e = 0; e < E_; e++) {
            float kv = kcol[e * KST];                       // stride-1 across lanes
            const float4* mrow = (const float4*)&s->M[e * H1_];
            #pragma unroll
            for (int q4 = 0; q4 < H1_ / 4; q4++) {          // LDS.128 broadcast: 4 FFMA / LDS
                float4 m = mrow[q4];
                acc[4 * q4 + 0] += kv * m.x;
                acc[4 * q4 + 1] += kv * m.y;
                acc[4 * q4 + 2] += kv * m.z;
                acc[4 * q4 + 3] += kv * m.w;
            }
        }
        #pragma unroll
        for (int h = 0; h < H1_; h++)
            acc[h] = __fdividef(1.f, 1.f + __expf(-acc[h]));

        float sc = 0.f;
        for (int j = 0; j < H2_; j++) {
            const float4* wrow = (const float4*)&s->W2t[j * H1_];
            float s0 = 0.f, s1 = 0.f, s2 = 0.f, s3 = 0.f;
            #pragma unroll
            for (int q4 = 0; q4 < H1_ / 4; q4++) {
                float4 w = wrow[q4];
                s0 += acc[4 * q4 + 0] * w.x;
                s1 += acc[4 * q4 + 1] * w.y;
                s2 += acc[4 * q4 + 2] * w.z;
                s3 += acc[4 * q4 + 3] * w.w;
            }
            float hp = s->B2[j] + ((s0 + s1) + (s2 + s3));
            float h2 = __fdividef(1.f, 1.f + __expf(-hp));
            sc += h2 * s->Wd[j];
        }
        score = sc + s->bd;
    }
    s->Score[tid] = score;
    __syncthreads();

    // Phase 3: pooling out[e] = sum_{t<len} score[t] * K[t][e]
    // Warp w handles t = w, w+NWARP, ...; lanes cover e = lane and lane+32.
    {
        float p0 = 0.f, p1 = 0.f;
        for (int t2 = wrp; t2 < len; t2 += NWARP) {
            float sv = s->Score[t2];                       // broadcast
            p0 += sv * s->K[lane        * KST + t2];       // conflict-free (stride 201)
            p1 += sv * s->K[(lane + 32) * KST + t2];
        }
        s->P[wrp * E_ + lane]      = p0;
        s->P[wrp * E_ + lane + 32] = p1;
    }
    __syncthreads();
    if (tid < E_) {
        float ssum = 0.f;
        #pragma unroll
        for (int w = 0; w < NWARP; w++) ssum += s->P[w * E_ + tid];
        out[b * E_ + tid] = ssum;   // len==0 -> writes required 0
    }
}

// ---------------------------------------------------------------------------
extern "C" void kernel_launch(void* const* d_in, const int* in_sizes, int n_in,
                              void* d_out, int out_size) {
    const float* query = (const float*)d_in[0];
    const float* keys  = (const float*)d_in[1];
    const int*   klen  = (const int*)  d_in[2];   // width auto-detected in prep
    const float* W1    = (const float*)d_in[3];
    const float* b1    = (const float*)d_in[4];
    const float* W2    = (const float*)d_in[5];
    const float* b2    = (const float*)d_in[6];
    const float* Wd    = (const float*)d_in[7];
    const float* bd    = (const float*)d_in[8];
    float* out = (float*)d_out;

    cudaFuncSetAttribute(din_kernel, cudaFuncAttributeMaxDynamicSharedMemorySize,
                         (int)sizeof(Smem));

    prep<<<21, 256>>>(W1, klen);
    din_kernel<<<B_, NTHR, sizeof(Smem)>>>(query, keys, b1, W2, b2, Wd, bd, out);
}

// round 4
// speedup vs baseline: 2.3918x; 2.1524x over previous
#include <cuda_runtime.h>
#include <cuda_fp16.h>
#include <math.h>

#define B_   4096
#define T_   200
#define E_   64
#define H1_  80
#define H2_  40
#define NT   256
#define HROWS 112          // rows per T-half tile (104 used + pad to 7 m16 tiles)
#define HALF  104

// strides (bytes): K/M rows = 72 halves = 144B (144%128=16 -> ldmatrix conflict-free)
//                  H/W2 rows = 88 halves = 176B (176%128=48 -> conflict-free)
#define KS  144
#define HS  176

// ---------------- smem layout (bytes)
#define OFF_KHI 0                       // [112][72]h  16128
#define OFF_KLO 16128                   // [112][72]h  16128
#define OFF_H   32256                   // [112][88]h  19712
#define OFF_MHI 51968                   // [80][72]h   11520
#define OFF_MLO 63488                   // [80][72]h   11520
#define OFF_W2  75008                   // [40][88]h    7040
#define OFF_C   82048                   // f32[80]
#define OFF_B2  82368                   // f32[40]
#define OFF_WD  82528                   // f32[40]
#define OFF_Q   82688                   // f32[64]
#define OFF_SC  82944                   // f32[112]
#define OFF_SP  83392                   // f32[8*64]
#define OFF_BD  85440
#define SMEM_TOTAL 85504

__device__ __forceinline__ unsigned smem_u32(const void* p) {
    unsigned a; asm("{ .reg .u64 t; cvta.to.shared.u64 t, %1; cvt.u32.u64 %0, t; }" : "=r"(a) : "l"(p));
    return a;
}
__device__ __forceinline__ void ldmx4(unsigned a[4], unsigned addr) {
    asm volatile("ldmatrix.sync.aligned.m8n8.x4.shared.b16 {%0,%1,%2,%3}, [%4];"
                 : "=r"(a[0]), "=r"(a[1]), "=r"(a[2]), "=r"(a[3]) : "r"(addr));
}
__device__ __forceinline__ void ldmx2(unsigned a[2], unsigned addr) {
    asm volatile("ldmatrix.sync.aligned.m8n8.x2.shared.b16 {%0,%1}, [%2];"
                 : "=r"(a[0]), "=r"(a[1]) : "r"(addr));
}
__device__ __forceinline__ void mma16816(float d[4], const unsigned a[4], const unsigned b[2]) {
    asm volatile("mma.sync.aligned.m16n8k16.row.col.f32.f16.f16.f32 "
                 "{%0,%1,%2,%3},{%4,%5,%6,%7},{%8,%9},{%0,%1,%2,%3};"
                 : "+f"(d[0]), "+f"(d[1]), "+f"(d[2]), "+f"(d[3])
                 : "r"(a[0]), "r"(a[1]), "r"(a[2]), "r"(a[3]), "r"(b[0]), "r"(b[1]));
}
__device__ __forceinline__ float sigf(float x) { return __fdividef(1.f, 1.f + __expf(-x)); }

// ---------------- device scratch
__device__ float    g_Wkt[H1_ * E_];   // (W1b - W1c)^T [h][e]
__device__ float    g_Wpt[H1_ * E_];   // W1d^T        [h][e]
__device__ float    g_Wqt[H1_ * E_];   // (W1a + W1c)^T[h][e]
__device__ unsigned g_W2h[1760];       // W2^T fp16 image [40 rows j][88 cols h], u32 words
__device__ int      g_len[B_];

// ---------------------------------------------------------------------------
__global__ void prep(const float* __restrict__ W1, const float* __restrict__ W2,
                     const int* __restrict__ raw) {
    int blk = blockIdx.x, tid = threadIdx.x;
    if (blk < 20) {                                   // W1 folds, transposed
        int idx = blk * 256 + tid;
        if (idx >= H1_ * E_) return;
        int h = idx >> 6, e = idx & 63;
        float wa = W1[(e         ) * H1_ + h];
        float wb = W1[(E_     + e) * H1_ + h];
        float wc = W1[(2 * E_ + e) * H1_ + h];
        float wd = W1[(3 * E_ + e) * H1_ + h];
        g_Wqt[idx] = wa + wc;
        g_Wkt[idx] = wb - wc;
        g_Wpt[idx] = wd;
    } else if (blk == 20) {                           // keys_length dtype sniff + clamp
        int any = 0;
        for (int i = 2 * tid + 1; i < B_; i += 512) any |= raw[i];
        int has_odd = __syncthreads_or(any);
        int is64 = (has_odd == 0);
        for (int i = tid; i < B_; i += 256) {
            int v = is64 ? raw[2 * i] : raw[i];
            g_len[i] = v < 0 ? 0 : (v > T_ ? T_ : v);
        }
    } else {                                          // W2^T fp16 image: word i = row j=i/44, h pair 2w
        int idx = (blk - 21) * 256 + tid;
        if (idx < 1760) {
            int j = idx / 44, w = idx - j * 44;
            int h0 = 2 * w;
            float v0 = (h0     < H1_) ? W2[h0 * H2_ + j]       : 0.f;
            float v1 = (h0 + 1 < H1_) ? W2[(h0 + 1) * H2_ + j] : 0.f;
            __half2 p = __floats2half2_rn(v0, v1);
            g_W2h[idx] = *(unsigned*)&p;
        }
    }
}

// ---------------------------------------------------------------------------
extern __shared__ char smem[];

__global__ void __launch_bounds__(NT, 2)
din_mma(const float* __restrict__ query, const float* __restrict__ keys,
        const float* __restrict__ b1v,   const float* __restrict__ b2v,
        const float* __restrict__ Wdv,   const float* __restrict__ bdv,
        float* __restrict__ out)
{
    const int tid  = threadIdx.x;
    const int wid  = tid >> 5;
    const int lane = tid & 31;
    const int b    = blockIdx.x;
    const int len  = g_len[b];
    const unsigned sb = smem_u32(smem);

    // ldmatrix / fragment lane constants
    const int g    = lane >> 2;
    const int t2   = (lane & 3) * 2;
    const int arow = (lane & 7) + ((lane >> 3) & 1) * 8;   // A-frag row within 16
    const int acolB = ((lane >> 4) * 8) * 2;               // A-frag k byte offset
    const int brow = lane & 7;                             // B-frag n row within 8
    const int bcolB = (((lane >> 3) & 1) * 8) * 2;         // B-frag k byte offset

    float* sQ  = (float*)(smem + OFF_Q);
    float* sC  = (float*)(smem + OFF_C);
    float* sB2 = (float*)(smem + OFF_B2);
    float* sWd = (float*)(smem + OFF_WD);
    float* sSc = (float*)(smem + OFF_SC);
    float* sSp = (float*)(smem + OFF_SP);

    // ---- phase 0: small vectors
    if (tid < E_) sQ[tid] = query[b * E_ + tid];
    if (tid >= 64 && tid < 64 + H2_) { int j = tid - 64; sB2[j] = b2v[j]; sWd[j] = Wdv[j]; }
    if (tid == 104) *(float*)(smem + OFF_BD) = bdv[0];
    __syncthreads();

    // ---- phase 1: M hi/lo, C, W2 copy
    for (int idx = tid; idx < H1_ * E_; idx += NT) {
        int h = idx >> 6, e = idx & 63;
        float v = g_Wkt[idx] + sQ[e] * g_Wpt[idx];
        __half hi = __float2half_rn(v);
        __half lo = __float2half_rn(v - __half2float(hi));
        *(__half*)(smem + OFF_MHI + h * KS + e * 2) = hi;
        *(__half*)(smem + OFF_MLO + h * KS + e * 2) = lo;
    }
    if (tid < H1_) {
        const float4* wq = (const float4*)&g_Wqt[tid * E_];
        const float4* q4 = (const float4*)sQ;
        float c = b1v[tid];
        #pragma unroll
        for (int i = 0; i < 16; i++) {
            float4 w = wq[i], q = q4[i];
            c += w.x * q.x + w.y * q.y + w.z * q.z + w.w * q.w;
        }
        sC[tid] = c;
    }
    for (int i = tid; i < 1760; i += NT) ((unsigned*)(smem + OFF_W2))[i] = g_W2h[i];
    __syncthreads();

    const float bd = *(float*)(smem + OFF_BD);
    float acc0 = 0.f, acc1 = 0.f;          // pooling accumulators (e = 2*lane, 2*lane+1)

    for (int hh = 0; hh < 2; hh++) {
        int hlen = len - HALF * hh;
        if (hlen > HALF) hlen = HALF;
        if (hlen <= 0) break;
        const int mt = (hlen + 15) >> 4;   // m16 tiles this half (<=7)

        // ---- load K half: fp32 -> fp16 hi/lo; zero rows [hlen,112)
        {
            int zcnt = (HROWS - hlen) * (KS / 4);
            unsigned* zh = (unsigned*)(smem + OFF_KHI + hlen * KS);
            unsigned* zl = (unsigned*)(smem + OFF_KLO + hlen * KS);
            for (int i = tid; i < zcnt; i += NT) { zh[i] = 0; zl[i] = 0; }
            const float4* kb = (const float4*)(keys + (size_t)b * (T_ * E_) + HALF * hh * E_);
            int n4 = hlen * 16;
            for (int i4 = tid; i4 < n4; i4 += NT) {
                float4 v = kb[i4];
                int tl = i4 >> 4, e4 = (i4 & 15) << 2;
                __half hx = __float2half_rn(v.x), hy = __float2half_rn(v.y);
                __half hz = __float2half_rn(v.z), hw = __float2half_rn(v.w);
                __half2 h0; h0.x = hx; h0.y = hy;
                __half2 h1; h1.x = hz; h1.y = hw;
                __half2 l0 = __floats2half2_rn(v.x - __half2float(hx), v.y - __half2float(hy));
                __half2 l1 = __floats2half2_rn(v.z - __half2float(hz), v.w - __half2float(hw));
                unsigned off = (unsigned)tl * KS + (unsigned)e4 * 2;
                *(uint2*)(smem + OFF_KHI + off) = make_uint2(*(unsigned*)&h0, *(unsigned*)&h1);
                *(uint2*)(smem + OFF_KLO + off) = make_uint2(*(unsigned*)&l0, *(unsigned*)&l1);
            }
        }
        __syncthreads();

        // ---- layer 1: (m,n) units round-robined over 8 warps; 3-pass fp16 emulation
        {
            int nunits = mt * 10;
            for (int u = wid; u < nunits; u += 8) {
                int mi = u / 10;
                int nt = u - mi * 10;
                float D[4] = {0.f, 0.f, 0.f, 0.f};
                unsigned aB = sb + OFF_KHI + (unsigned)(mi * 16 + arow) * KS + acolB;
                unsigned bB = sb + OFF_MHI + (unsigned)(nt * 8 + brow) * KS + bcolB;
                #pragma unroll
                for (int kt = 0; kt < 4; kt++) {
                    unsigned Ah[4], Al[4], Bh[2], Bl[2];
                    ldmx4(Ah, aB + kt * 32);
                    ldmx4(Al, aB + kt * 32 + (OFF_KLO - OFF_KHI));
                    ldmx2(Bh, bB + kt * 32);
                    ldmx2(Bl, bB + kt * 32 + (OFF_MLO - OFF_MHI));
                    mma16816(D, Ah, Bh);
                    mma16816(D, Al, Bh);
                    mma16816(D, Ah, Bl);
                }
                // epilogue: +C, sigmoid, pack fp16 -> H
                float c0 = sC[nt * 8 + t2], c1 = sC[nt * 8 + t2 + 1];
                __half2 r0 = __floats2half2_rn(sigf(D[0] + c0), sigf(D[1] + c1));
                __half2 r1 = __floats2half2_rn(sigf(D[2] + c0), sigf(D[3] + c1));
                unsigned colB = (unsigned)(nt * 8 + t2) * 2;
                *(unsigned*)(smem + OFF_H + (unsigned)(mi * 16 + g    ) * HS + colB) = *(unsigned*)&r0;
                *(unsigned*)(smem + OFF_H + (unsigned)(mi * 16 + g + 8) * HS + colB) = *(unsigned*)&r1;
            }
        }
        __syncthreads();

        // ---- layer 2: warp w handles m-tile w; 5 n-tiles x 5 k-tiles, single fp16
        if (wid < mt) {
            float D[5][4];
            #pragma unroll
            for (int n = 0; n < 5; n++)
                #pragma unroll
                for (int r = 0; r < 4; r++) D[n][r] = 0.f;
            unsigned aB = sb + OFF_H + (unsigned)(wid * 16 + arow) * HS + acolB;
            #pragma unroll
            for (int kt = 0; kt < 5; kt++) {
                unsigned A[4];
                ldmx4(A, aB + kt * 32);
                #pragma unroll
                for (int n = 0; n < 5; n++) {
                    unsigned Bf[2];
                    ldmx2(Bf, sb + OFF_W2 + (unsigned)(n * 8 + brow) * HS + (unsigned)(kt * 32) + bcolB);
                    mma16816(D[n], A, Bf);
                }
            }
            float p0 = 0.f, p1 = 0.f;
            #pragma unroll
            for (int n = 0; n < 5; n++) {
                int j0 = n * 8 + t2;
                float w0 = sWd[j0], w1 = sWd[j0 + 1];
                float bb0 = sB2[j0], bb1 = sB2[j0 + 1];
                p0 += sigf(D[n][0] + bb0) * w0 + sigf(D[n][1] + bb1) * w1;
                p1 += sigf(D[n][2] + bb0) * w0 + sigf(D[n][3] + bb1) * w1;
            }
            p0 += __shfl_xor_sync(0xFFFFFFFFu, p0, 1);
            p0 += __shfl_xor_sync(0xFFFFFFFFu, p0, 2);
            p1 += __shfl_xor_sync(0xFFFFFFFFu, p1, 1);
            p1 += __shfl_xor_sync(0xFFFFFFFFu, p1, 2);
            if ((lane & 3) == 0) {
                sSc[wid * 16 + g]     = p0 + bd;
                sSc[wid * 16 + g + 8] = p1 + bd;
            }
        }
        __syncthreads();

        // ---- pooling accumulate: out[e] += sum_{t<hlen} score[t] * (khi+klo)[t][e]
        for (int t = wid; t < hlen; t += 8) {
            float sv = sSc[t];
            unsigned uh = *(unsigned*)(smem + OFF_KHI + (unsigned)t * KS + lane * 4);
            unsigned ul = *(unsigned*)(smem + OFF_KLO + (unsigned)t * KS + lane * 4);
            float2 kh = __half22float2(*(__half2*)&uh);
            float2 kl = __half22float2(*(__half2*)&ul);
            acc0 += sv * (kh.x + kl.x);
            acc1 += sv * (kh.y + kl.y);
        }
        __syncthreads();   // protect K/H/scores before next half overwrites
    }

    // ---- final reduce across warps
    sSp[wid * 64 + 2 * lane]     = acc0;
    sSp[wid * 64 + 2 * lane + 1] = acc1;
    __syncthreads();
    if (tid < E_) {
        float o = 0.f;
        #pragma unroll
        for (int w = 0; w < 8; w++) o += sSp[w * 64 + tid];
        out[b * E_ + tid] = o;
    }
}

// ---------------------------------------------------------------------------
extern "C" void kernel_launch(void* const* d_in, const int* in_sizes, int n_in,
                              void* d_out, int out_size) {
    const float* query = (const float*)d_in[0];
    const float* keys  = (const float*)d_in[1];
    const int*   klen  = (const int*)  d_in[2];
    const float* W1    = (const float*)d_in[3];
    const float* b1    = (const float*)d_in[4];
    const float* W2    = (const float*)d_in[5];
    const float* b2    = (const float*)d_in[6];
    const float* Wd    = (const float*)d_in[7];
    const float* bd    = (const float*)d_in[8];
    float* out = (float*)d_out;

    cudaFuncSetAttribute(din_mma, cudaFuncAttributeMaxDynamicSharedMemorySize, SMEM_TOTAL);

    prep<<<28, 256>>>(W1, W2, klen);
    din_mma<<<B_, NT, SMEM_TOTAL>>>(query, keys, b1, b2, Wd, bd, out);
}

// round 5
// speedup vs baseline: 3.1742x; 1.3271x over previous
#include <cuda_runtime.h>
#include <cuda_fp16.h>
#include <math.h>

#define B_   4096
#define T_   200
#define E_   64
#define H1_  80
#define H2_  40
#define NT   256
#define HROWS 112
#define HALF  104

// strides (bytes): K/M rows = 144B (144%128=16 -> ldmatrix conflict-free)
//                  H/W2 rows = 176B (176%128=48 -> conflict-free)
#define KS  144
#define HS  176

// ---------------- smem layout (bytes)
#define OFF_KHI 0                       // [112][72]h  16128
#define OFF_H   16128                   // [112][88]h  19712
#define OFF_MHI 35840                   // [80][72]h   11520
#define OFF_MLO 47360                   // [80][72]h   11520
#define OFF_W2  58880                   // [40][88]h    7040
#define OFF_C   65920                   // f32[80]
#define OFF_B2  66240                   // f32[40]
#define OFF_WD  66400                   // f32[40]
#define OFF_Q   66560                   // f32[64]
#define OFF_SC  66816                   // f32[112]
#define OFF_SP  67264                   // f32[8*64]
#define OFF_BD  69312
#define SMEM_TOTAL 69376                // x3 CTAs = 208KB <= 228KB/SM

__device__ __forceinline__ unsigned smem_u32(const void* p) {
    unsigned a; asm("{ .reg .u64 t; cvta.to.shared.u64 t, %1; cvt.u32.u64 %0, t; }" : "=r"(a) : "l"(p));
    return a;
}
__device__ __forceinline__ void ldmx4(unsigned a[4], unsigned addr) {
    asm volatile("ldmatrix.sync.aligned.m8n8.x4.shared.b16 {%0,%1,%2,%3}, [%4];"
                 : "=r"(a[0]), "=r"(a[1]), "=r"(a[2]), "=r"(a[3]) : "r"(addr));
}
__device__ __forceinline__ void ldmx2(unsigned a[2], unsigned addr) {
    asm volatile("ldmatrix.sync.aligned.m8n8.x2.shared.b16 {%0,%1}, [%2];"
                 : "=r"(a[0]), "=r"(a[1]) : "r"(addr));
}
__device__ __forceinline__ void mma16816(float d[4], const unsigned a[4], const unsigned b[2]) {
    asm volatile("mma.sync.aligned.m16n8k16.row.col.f32.f16.f16.f32 "
                 "{%0,%1,%2,%3},{%4,%5,%6,%7},{%8,%9},{%0,%1,%2,%3};"
                 : "+f"(d[0]), "+f"(d[1]), "+f"(d[2]), "+f"(d[3])
                 : "r"(a[0]), "r"(a[1]), "r"(a[2]), "r"(a[3]), "r"(b[0]), "r"(b[1]));
}
__device__ __forceinline__ float sigf(float x) { return __fdividef(1.f, 1.f + __expf(-x)); }

// ---------------- device scratch
__device__ float    g_Wkt[H1_ * E_];   // (W1b - W1c)^T [h][e]
__device__ float    g_Wpt[H1_ * E_];   // W1d^T        [h][e]
__device__ float    g_Wqt[H1_ * E_];   // (W1a + W1c)^T[h][e]
__device__ unsigned g_W2h[1760];       // W2^T fp16 image [40 rows j][88 cols h], u32 words
__device__ int      g_len[B_];

// ---------------------------------------------------------------------------
__global__ void prep(const float* __restrict__ W1, const float* __restrict__ W2,
                     const int* __restrict__ raw) {
    int blk = blockIdx.x, tid = threadIdx.x;
    if (blk < 20) {                                   // W1 folds, transposed
        int idx = blk * 256 + tid;
        if (idx >= H1_ * E_) return;
        int h = idx >> 6, e = idx & 63;
        float wa = W1[(e         ) * H1_ + h];
        float wb = W1[(E_     + e) * H1_ + h];
        float wc = W1[(2 * E_ + e) * H1_ + h];
        float wd = W1[(3 * E_ + e) * H1_ + h];
        g_Wqt[idx] = wa + wc;
        g_Wkt[idx] = wb - wc;
        g_Wpt[idx] = wd;
    } else if (blk == 20) {                           // keys_length dtype sniff + clamp
        int any = 0;
        for (int i = 2 * tid + 1; i < B_; i += 512) any |= raw[i];
        int has_odd = __syncthreads_or(any);
        int is64 = (has_odd == 0);
        for (int i = tid; i < B_; i += 256) {
            int v = is64 ? raw[2 * i] : raw[i];
            g_len[i] = v < 0 ? 0 : (v > T_ ? T_ : v);
        }
    } else {                                          // W2^T fp16 image
        int idx = (blk - 21) * 256 + tid;
        if (idx < 1760) {
            int j = idx / 44, w = idx - j * 44;
            int h0 = 2 * w;
            float v0 = (h0     < H1_) ? W2[h0 * H2_ + j]       : 0.f;
            float v1 = (h0 + 1 < H1_) ? W2[(h0 + 1) * H2_ + j] : 0.f;
            __half2 p = __floats2half2_rn(v0, v1);
            g_W2h[idx] = *(unsigned*)&p;
        }
    }
}

// ---------------------------------------------------------------------------
extern __shared__ char smem[];

__global__ void __launch_bounds__(NT, 3)
din_mma(const float* __restrict__ query, const float* __restrict__ keys,
        const float* __restrict__ b1v,   const float* __restrict__ b2v,
        const float* __restrict__ Wdv,   const float* __restrict__ bdv,
        float* __restrict__ out)
{
    const int tid  = threadIdx.x;
    const int wid  = tid >> 5;
    const int lane = tid & 31;
    const int b    = blockIdx.x;
    const int len  = g_len[b];
    const unsigned sb = smem_u32(smem);

    // fragment lane constants
    const int g     = lane >> 2;
    const int t2    = (lane & 3) * 2;
    const int arow  = (lane & 7) + ((lane >> 3) & 1) * 8;
    const int acolB = ((lane >> 4) * 8) * 2;
    const int brow  = lane & 7;
    const int bcolB = (((lane >> 3) & 1) * 8) * 2;

    float* sQ  = (float*)(smem + OFF_Q);
    float* sC  = (float*)(smem + OFF_C);
    float* sB2 = (float*)(smem + OFF_B2);
    float* sWd = (float*)(smem + OFF_WD);
    float* sSc = (float*)(smem + OFF_SC);
    float* sSp = (float*)(smem + OFF_SP);

    // ---- phase 0: small vectors
    if (tid < E_) sQ[tid] = query[b * E_ + tid];
    if (tid >= 64 && tid < 64 + H2_) { int j = tid - 64; sB2[j] = b2v[j]; sWd[j] = Wdv[j]; }
    if (tid == 104) *(float*)(smem + OFF_BD) = bdv[0];
    __syncthreads();

    // ---- phase 1: M hi/lo, C, W2 copy
    for (int idx = tid; idx < H1_ * E_; idx += NT) {
        int h = idx >> 6, e = idx & 63;
        float v = g_Wkt[idx] + sQ[e] * g_Wpt[idx];
        __half hi = __float2half_rn(v);
        __half lo = __float2half_rn(v - __half2float(hi));
        *(__half*)(smem + OFF_MHI + h * KS + e * 2) = hi;
        *(__half*)(smem + OFF_MLO + h * KS + e * 2) = lo;
    }
    if (tid < H1_) {
        const float4* wq = (const float4*)&g_Wqt[tid * E_];
        const float4* q4 = (const float4*)sQ;
        float c = b1v[tid];
        #pragma unroll
        for (int i = 0; i < 16; i++) {
            float4 w = wq[i], q = q4[i];
            c += w.x * q.x + w.y * q.y + w.z * q.z + w.w * q.w;
        }
        sC[tid] = c;
    }
    for (int i = tid; i < 1760; i += NT) ((unsigned*)(smem + OFF_W2))[i] = g_W2h[i];
    __syncthreads();

    const float bd = *(float*)(smem + OFF_BD);
    float acc0 = 0.f, acc1 = 0.f;          // pooling accumulators (e = 2*lane, 2*lane+1)

    for (int hh = 0; hh < 2; hh++) {
        int hlen = len - HALF * hh;
        if (hlen > HALF) hlen = HALF;
        if (hlen <= 0) break;
        const int mt = (hlen + 15) >> 4;   // m16 tiles this half (<=7)

        // ---- load K half: fp32 -> fp16 hi only; zero rows [hlen,112)
        {
            int zcnt = (HROWS - hlen) * (KS / 4);
            unsigned* zh = (unsigned*)(smem + OFF_KHI + hlen * KS);
            for (int i = tid; i < zcnt; i += NT) zh[i] = 0;
            const float4* kb = (const float4*)(keys + (size_t)b * (T_ * E_) + HALF * hh * E_);
            int n4 = hlen * 16;
            for (int i4 = tid; i4 < n4; i4 += NT) {
                float4 v = kb[i4];
                int tl = i4 >> 4, e4 = (i4 & 15) << 2;
                __half2 h0 = __floats2half2_rn(v.x, v.y);
                __half2 h1 = __floats2half2_rn(v.z, v.w);
                *(uint2*)(smem + OFF_KHI + (unsigned)tl * KS + (unsigned)e4 * 2) =
                    make_uint2(*(unsigned*)&h0, *(unsigned*)&h1);
            }
        }
        __syncthreads();

        // ---- layer 1: units = (mi, 5-nt group); A loaded once per unit, 2-pass (Mhi+Mlo)
        {
            int nunits = mt * 2;
            for (int u = wid; u < nunits; u += 8) {
                int mi  = u >> 1;
                int grp = (u & 1) * 5;
                unsigned Ah[4][4];
                unsigned aB = sb + OFF_KHI + (unsigned)(mi * 16 + arow) * KS + acolB;
                #pragma unroll
                for (int kt = 0; kt < 4; kt++) ldmx4(Ah[kt], aB + kt * 32);
                #pragma unroll
                for (int nn = 0; nn < 5; nn++) {
                    int nt = grp + nn;
                    float D[4] = {0.f, 0.f, 0.f, 0.f};
                    unsigned bB = sb + OFF_MHI + (unsigned)(nt * 8 + brow) * KS + bcolB;
                    #pragma unroll
                    for (int kt = 0; kt < 4; kt++) {
                        unsigned Bh[2], Bl[2];
                        ldmx2(Bh, bB + kt * 32);
                        ldmx2(Bl, bB + kt * 32 + (OFF_MLO - OFF_MHI));
                        mma16816(D, Ah[kt], Bh);
                        mma16816(D, Ah[kt], Bl);
                    }
                    float c0 = sC[nt * 8 + t2], c1 = sC[nt * 8 + t2 + 1];
                    __half2 r0 = __floats2half2_rn(sigf(D[0] + c0), sigf(D[1] + c1));
                    __half2 r1 = __floats2half2_rn(sigf(D[2] + c0), sigf(D[3] + c1));
                    unsigned colB = (unsigned)(nt * 8 + t2) * 2;
                    *(unsigned*)(smem + OFF_H + (unsigned)(mi * 16 + g    ) * HS + colB) = *(unsigned*)&r0;
                    *(unsigned*)(smem + OFF_H + (unsigned)(mi * 16 + g + 8) * HS + colB) = *(unsigned*)&r1;
                }
            }
        }
        __syncthreads();

        // ---- layer 2: warp w handles m-tile w; 5 n-tiles x 5 k-tiles, single fp16
        if (wid < mt) {
            float D[5][4];
            #pragma unroll
            for (int n = 0; n < 5; n++)
                #pragma unroll
                for (int r = 0; r < 4; r++) D[n][r] = 0.f;
            unsigned aB = sb + OFF_H + (unsigned)(wid * 16 + arow) * HS + acolB;
            #pragma unroll
            for (int kt = 0; kt < 5; kt++) {
                unsigned A[4];
                ldmx4(A, aB + kt * 32);
                #pragma unroll
                for (int n = 0; n < 5; n++) {
                    unsigned Bf[2];
                    ldmx2(Bf, sb + OFF_W2 + (unsigned)(n * 8 + brow) * HS + (unsigned)(kt * 32) + bcolB);
                    mma16816(D[n], A, Bf);
                }
            }
            float p0 = 0.f, p1 = 0.f;
            #pragma unroll
            for (int n = 0; n < 5; n++) {
                int j0 = n * 8 + t2;
                float w0 = sWd[j0], w1 = sWd[j0 + 1];
                float bb0 = sB2[j0], bb1 = sB2[j0 + 1];
                p0 += sigf(D[n][0] + bb0) * w0 + sigf(D[n][1] + bb1) * w1;
                p1 += sigf(D[n][2] + bb0) * w0 + sigf(D[n][3] + bb1) * w1;
            }
            p0 += __shfl_xor_sync(0xFFFFFFFFu, p0, 1);
            p0 += __shfl_xor_sync(0xFFFFFFFFu, p0, 2);
            p1 += __shfl_xor_sync(0xFFFFFFFFu, p1, 1);
            p1 += __shfl_xor_sync(0xFFFFFFFFu, p1, 2);
            if ((lane & 3) == 0) {
                sSc[wid * 16 + g]     = p0 + bd;
                sSc[wid * 16 + g + 8] = p1 + bd;
            }
        }
        __syncthreads();

        // ---- pooling: out[e] += sum_{t<hlen} score[t] * keys[t][e]  (exact fp32, L2-hot)
        {
            const float* kb2 = keys + (size_t)b * (T_ * E_) + HALF * hh * E_;
            for (int t = wid; t < hlen; t += 8) {
                float sv = sSc[t];
                float2 kv = *(const float2*)(kb2 + (size_t)t * E_ + 2 * lane);
                acc0 += sv * kv.x;
                acc1 += sv * kv.y;
            }
        }
        __syncthreads();   // protect K/H/scores before next half overwrites
    }

    // ---- final reduce across warps
    sSp[wid * 64 + 2 * lane]     = acc0;
    sSp[wid * 64 + 2 * lane + 1] = acc1;
    __syncthreads();
    if (tid < E_) {
        float o = 0.f;
        #pragma unroll
        for (int w = 0; w < 8; w++) o += sSp[w * 64 + tid];
        out[b * E_ + tid] = o;
    }
}

// ---------------------------------------------------------------------------
extern "C" void kernel_launch(void* const* d_in, const int* in_sizes, int n_in,
                              void* d_out, int out_size) {
    const float* query = (const float*)d_in[0];
    const float* keys  = (const float*)d_in[1];
    const int*   klen  = (const int*)  d_in[2];
    const float* W1    = (const float*)d_in[3];
    const float* b1    = (const float*)d_in[4];
    const float* W2    = (const float*)d_in[5];
    const float* b2    = (const float*)d_in[6];
    const float* Wd    = (const float*)d_in[7];
    const float* bd    = (const float*)d_in[8];
    float* out = (float*)d_out;

    cudaFuncSetAttribute(din_mma, cudaFuncAttributeMaxDynamicSharedMemorySize, SMEM_TOTAL);

    prep<<<28, 256>>>(W1, W2, klen);
    din_mma<<<B_, NT, SMEM_TOTAL>>>(query, keys, b1, b2, Wd, bd, out);
}

// round 6
// speedup vs baseline: 3.5776x; 1.1271x over previous
#include <cuda_runtime.h>
#include <cuda_fp16.h>
#include <math.h>

#define B_   4096
#define T_   200
#define E_   64
#define H1_  80
#define H2_  40
#define NT   256
#define HROWS 128
#define HALF  128

// strides (bytes): K/M rows = 144B (144%128=16 -> ldmatrix conflict-free)
//                  W2 rows  = 176B (176%128=48 -> conflict-free)
#define KS  144
#define HS  176

// ---------------- smem layout (bytes)
#define OFF_K   0                       // [128][72]h  18432
#define OFF_MHI 18432                   // [80][72]h   11520
#define OFF_MLO 29952                   // [80][72]h   11520
#define OFF_W2  41472                   // [40][88]h    7040
#define OFF_C   48512                   // f32[80]
#define OFF_B2  48832                   // f32[40]
#define OFF_WD  48992                   // f32[40]
#define OFF_Q   49152                   // f32[64]
#define OFF_SC  49408                   // f32[128]
#define OFF_SP  49920                   // f32[8*64]
#define OFF_BD  51968
#define SMEM_TOTAL 52096                // x3 CTAs = 156KB <= 228KB/SM

__device__ __forceinline__ unsigned smem_u32(const void* p) {
    unsigned a; asm("{ .reg .u64 t; cvta.to.shared.u64 t, %1; cvt.u32.u64 %0, t; }" : "=r"(a) : "l"(p));
    return a;
}
__device__ __forceinline__ void ldmx4(unsigned a[4], unsigned addr) {
    asm volatile("ldmatrix.sync.aligned.m8n8.x4.shared.b16 {%0,%1,%2,%3}, [%4];"
                 : "=r"(a[0]), "=r"(a[1]), "=r"(a[2]), "=r"(a[3]) : "r"(addr));
}
__device__ __forceinline__ void ldmx2(unsigned a[2], unsigned addr) {
    asm volatile("ldmatrix.sync.aligned.m8n8.x2.shared.b16 {%0,%1}, [%2];"
                 : "=r"(a[0]), "=r"(a[1]) : "r"(addr));
}
__device__ __forceinline__ void mma16816(float d[4], const unsigned a[4], const unsigned b[2]) {
    asm volatile("mma.sync.aligned.m16n8k16.row.col.f32.f16.f16.f32 "
                 "{%0,%1,%2,%3},{%4,%5,%6,%7},{%8,%9},{%0,%1,%2,%3};"
                 : "+f"(d[0]), "+f"(d[1]), "+f"(d[2]), "+f"(d[3])
                 : "r"(a[0]), "r"(a[1]), "r"(a[2]), "r"(a[3]), "r"(b[0]), "r"(b[1]));
}
__device__ __forceinline__ float sigf(float x) { return __fdividef(1.f, 1.f + __expf(-x)); }

// ---------------- device scratch
__device__ float    g_Wkt[H1_ * E_];   // (W1b - W1c)^T [h][e]
__device__ float    g_Wpt[H1_ * E_];   // W1d^T        [h][e]
__device__ float    g_Wqt[H1_ * E_];   // (W1a + W1c)^T[h][e]
__device__ unsigned g_W2h[1760];       // W2^T fp16 image [40 rows j][88 cols h], u32 words
__device__ int      g_len[B_];

// ---------------------------------------------------------------------------
__global__ void prep(const float* __restrict__ W1, const float* __restrict__ W2,
                     const int* __restrict__ raw) {
    int blk = blockIdx.x, tid = threadIdx.x;
    if (blk < 20) {                                   // W1 folds, transposed
        int idx = blk * 256 + tid;
        if (idx >= H1_ * E_) return;
        int h = idx >> 6, e = idx & 63;
        float wa = W1[(e         ) * H1_ + h];
        float wb = W1[(E_     + e) * H1_ + h];
        float wc = W1[(2 * E_ + e) * H1_ + h];
        float wd = W1[(3 * E_ + e) * H1_ + h];
        g_Wqt[idx] = wa + wc;
        g_Wkt[idx] = wb - wc;
        g_Wpt[idx] = wd;
    } else if (blk == 20) {                           // keys_length dtype sniff + clamp
        int any = 0;
        for (int i = 2 * tid + 1; i < B_; i += 512) any |= raw[i];
        int has_odd = __syncthreads_or(any);
        int is64 = (has_odd == 0);
        for (int i = tid; i < B_; i += 256) {
            int v = is64 ? raw[2 * i] : raw[i];
            g_len[i] = v < 0 ? 0 : (v > T_ ? T_ : v);
        }
    } else {                                          // W2^T fp16 image
        int idx = (blk - 21) * 256 + tid;
        if (idx < 1760) {
            int j = idx / 44, w = idx - j * 44;
            int h0 = 2 * w;
            float v0 = (h0     < H1_) ? W2[h0 * H2_ + j]       : 0.f;
            float v1 = (h0 + 1 < H1_) ? W2[(h0 + 1) * H2_ + j] : 0.f;
            __half2 p = __floats2half2_rn(v0, v1);
            g_W2h[idx] = *(unsigned*)&p;
        }
    }
}

// ---------------------------------------------------------------------------
extern __shared__ char smem[];

__global__ void __launch_bounds__(NT, 3)
din_mma(const float* __restrict__ query, const float* __restrict__ keys,
        const float* __restrict__ b1v,   const float* __restrict__ b2v,
        const float* __restrict__ Wdv,   const float* __restrict__ bdv,
        float* __restrict__ out)
{
    const int tid  = threadIdx.x;
    const int wid  = tid >> 5;
    const int lane = tid & 31;
    const int b    = blockIdx.x;
    const int len  = g_len[b];
    const unsigned sb = smem_u32(smem);

    // fragment lane constants
    const int g     = lane >> 2;
    const int t2    = (lane & 3) * 2;
    const int arow  = (lane & 7) + ((lane >> 3) & 1) * 8;
    const int acolB = ((lane >> 4) * 8) * 2;
    const int brow  = lane & 7;
    const int bcolB = (((lane >> 3) & 1) * 8) * 2;

    float* sQ  = (float*)(smem + OFF_Q);
    float* sC  = (float*)(smem + OFF_C);
    float* sB2 = (float*)(smem + OFF_B2);
    float* sWd = (float*)(smem + OFF_WD);
    float* sSc = (float*)(smem + OFF_SC);
    float* sSp = (float*)(smem + OFF_SP);

    // ---- phase 0: small vectors
    if (tid < E_) sQ[tid] = query[b * E_ + tid];
    if (tid >= 64 && tid < 64 + H2_) { int j = tid - 64; sB2[j] = b2v[j]; sWd[j] = Wdv[j]; }
    if (tid == 104) *(float*)(smem + OFF_BD) = bdv[0];
    __syncthreads();

    // ---- phase 1: M hi/lo, C, W2 copy
    for (int idx = tid; idx < H1_ * E_; idx += NT) {
        int h = idx >> 6, e = idx & 63;
        float v = g_Wkt[idx] + sQ[e] * g_Wpt[idx];
        __half hi = __float2half_rn(v);
        __half lo = __float2half_rn(v - __half2float(hi));
        *(__half*)(smem + OFF_MHI + h * KS + e * 2) = hi;
        *(__half*)(smem + OFF_MLO + h * KS + e * 2) = lo;
    }
    if (tid < H1_) {
        const float4* wq = (const float4*)&g_Wqt[tid * E_];
        const float4* q4 = (const float4*)sQ;
        float c = b1v[tid];
        #pragma unroll
        for (int i = 0; i < 16; i++) {
            float4 w = wq[i], q = q4[i];
            c += w.x * q.x + w.y * q.y + w.z * q.z + w.w * q.w;
        }
        sC[tid] = c;
    }
    for (int i = tid; i < 1760; i += NT) ((unsigned*)(smem + OFF_W2))[i] = g_W2h[i];
    __syncthreads();

    const float bd = *(float*)(smem + OFF_BD);
    float acc0 = 0.f, acc1 = 0.f;          // pooling accumulators (e = 2*lane, 2*lane+1)

    for (int hh = 0; hh < 2; hh++) {
        int hlen = len - HALF * hh;
        if (hlen > HALF) hlen = HALF;
        if (hlen <= 0) break;
        const int mt = (hlen + 15) >> 4;   // m16 tiles this half (<=8)

        // ---- convert K half: fp32 -> fp16; zero rows [hlen,128)
        {
            int zcnt = (HROWS - hlen) * (KS / 4);
            unsigned* zh = (unsigned*)(smem + OFF_K + hlen * KS);
            for (int i = tid; i < zcnt; i += NT) zh[i] = 0;
            const float4* kb = (const float4*)(keys + (size_t)b * (T_ * E_) + HALF * hh * E_);
            int n4 = hlen * 16;
            for (int i4 = tid; i4 < n4; i4 += NT) {
                float4 v = kb[i4];
                int tl = i4 >> 4, e4 = (i4 & 15) << 2;
                __half2 h0 = __floats2half2_rn(v.x, v.y);
                __half2 h1 = __floats2half2_rn(v.z, v.w);
                *(uint2*)(smem + OFF_K + (unsigned)tl * KS + (unsigned)e4 * 2) =
                    make_uint2(*(unsigned*)&h0, *(unsigned*)&h1);
            }
        }
        __syncthreads();

        // ---- fused layer1+layer2: warp w owns m-tile w through both layers.
        // Layer-1 accumulator fragments are repacked in-register as layer-2 A
        // fragments (C-layout == A-layout for paired n-tiles): H never hits smem.
        if (wid < mt) {
            unsigned Ah[4][4];
            unsigned aB = sb + OFF_K + (unsigned)(wid * 16 + arow) * KS + acolB;
            #pragma unroll
            for (int kt = 0; kt < 4; kt++) ldmx4(Ah[kt], aB + kt * 32);

            float D2[5][4];
            #pragma unroll
            for (int n = 0; n < 5; n++)
                #pragma unroll
                for (int r = 0; r < 4; r++) D2[n][r] = 0.f;

            #pragma unroll
            for (int kc = 0; kc < 5; kc++) {           // k-chunk = nt pair (2kc, 2kc+1)
                float De[4] = {0.f,0.f,0.f,0.f};
                float Do[4] = {0.f,0.f,0.f,0.f};
                unsigned bBe = sb + OFF_MHI + (unsigned)(kc * 16 + brow) * KS + bcolB;
                unsigned bBo = bBe + 8 * KS;
                #pragma unroll
                for (int kt = 0; kt < 4; kt++) {
                    unsigned Bh[2], Bl[2];
                    ldmx2(Bh, bBe + kt * 32);
                    ldmx2(Bl, bBe + kt * 32 + (OFF_MLO - OFF_MHI));
                    mma16816(De, Ah[kt], Bh);
                    mma16816(De, Ah[kt], Bl);
                    ldmx2(Bh, bBo + kt * 32);
                    ldmx2(Bl, bBo + kt * 32 + (OFF_MLO - OFF_MHI));
                    mma16816(Do, Ah[kt], Bh);
                    mma16816(Do, Ah[kt], Bl);
                }
                // epilogue -> A2 fragment (rows g/g+8, k16 chunk kc of layer-2)
                int ce = kc * 16 + t2;
                float c0 = sC[ce], c1 = sC[ce + 1], c2 = sC[ce + 8], c3 = sC[ce + 9];
                __half2 a0 = __floats2half2_rn(sigf(De[0] + c0), sigf(De[1] + c1));
                __half2 a1 = __floats2half2_rn(sigf(De[2] + c0), sigf(De[3] + c1));
                __half2 a2 = __floats2half2_rn(sigf(Do[0] + c2), sigf(Do[1] + c3));
                __half2 a3 = __floats2half2_rn(sigf(Do[2] + c2), sigf(Do[3] + c3));
                unsigned A2[4] = { *(unsigned*)&a0, *(unsigned*)&a1,
                                   *(unsigned*)&a2, *(unsigned*)&a3 };
                #pragma unroll
                for (int n = 0; n < 5; n++) {
                    unsigned Bw[2];
                    ldmx2(Bw, sb + OFF_W2 + (unsigned)(n * 8 + brow) * HS + (unsigned)(kc * 32) + bcolB);
                    mma16816(D2[n], A2, Bw);
                }
            }

            // ---- scores: sigmoid(D2 + b2) . Wd, reduce over n within lane quad
            float p0 = 0.f, p1 = 0.f;
            #pragma unroll
            for (int n = 0; n < 5; n++) {
                int j0 = n * 8 + t2;
                float w0 = sWd[j0], w1 = sWd[j0 + 1];
                float bb0 = sB2[j0], bb1 = sB2[j0 + 1];
                p0 += sigf(D2[n][0] + bb0) * w0 + sigf(D2[n][1] + bb1) * w1;
                p1 += sigf(D2[n][2] + bb0) * w0 + sigf(D2[n][3] + bb1) * w1;
            }
            p0 += __shfl_xor_sync(0xFFFFFFFFu, p0, 1);
            p0 += __shfl_xor_sync(0xFFFFFFFFu, p0, 2);
            p1 += __shfl_xor_sync(0xFFFFFFFFu, p1, 1);
            p1 += __shfl_xor_sync(0xFFFFFFFFu, p1, 2);
            if ((lane & 3) == 0) {
                sSc[wid * 16 + g]     = p0 + bd;
                sSc[wid * 16 + g + 8] = p1 + bd;
            }
        }
        __syncthreads();

        // ---- pooling: out[e] += sum_{t<hlen} score[t] * keys[t][e]  (exact fp32, L2-hot)
        {
            const float* kb2 = keys + (size_t)b * (T_ * E_) + HALF * hh * E_;
            for (int t = wid; t < hlen; t += 8) {
                float sv = sSc[t];
                float2 kv = *(const float2*)(kb2 + (size_t)t * E_ + 2 * lane);
                acc0 += sv * kv.x;
                acc1 += sv * kv.y;
            }
        }
        // no barrier needed: next phase writes only K (not read here), and the
        // next sSc write is behind the post-convert barrier.
    }

    // ---- final reduce across warps
    sSp[wid * 64 + 2 * lane]     = acc0;
    sSp[wid * 64 + 2 * lane + 1] = acc1;
    __syncthreads();
    if (tid < E_) {
        float o = 0.f;
        #pragma unroll
        for (int w = 0; w < 8; w++) o += sSp[w * 64 + tid];
        out[b * E_ + tid] = o;
    }
}

// ---------------------------------------------------------------------------
extern "C" void kernel_launch(void* const* d_in, const int* in_sizes, int n_in,
                              void* d_out, int out_size) {
    const float* query = (const float*)d_in[0];
    const float* keys  = (const float*)d_in[1];
    const int*   klen  = (const int*)  d_in[2];
    const float* W1    = (const float*)d_in[3];
    const float* b1    = (const float*)d_in[4];
    const float* W2    = (const float*)d_in[5];
    const float* b2    = (const float*)d_in[6];
    const float* Wd    = (const float*)d_in[7];
    const float* bd    = (const float*)d_in[8];
    float* out = (float*)d_out;

    cudaFuncSetAttribute(din_mma, cudaFuncAttributeMaxDynamicSharedMemorySize, SMEM_TOTAL);

    prep<<<28, 256>>>(W1, W2, klen);
    din_mma<<<B_, NT, SMEM_TOTAL>>>(query, keys, b1, b2, Wd, bd, out);
}

// round 7
// speedup vs baseline: 3.6290x; 1.0144x over previous
#include <cuda_runtime.h>
#include <cuda_fp16.h>
#include <math.h>

#define B_   4096
#define T_   200
#define E_   64
#define H1_  80
#define H2_  40
#define NT   256
#define HROWS 128
#define HALF  128

// strides (bytes): K/M rows = 144B (144%128=16 -> ldmatrix conflict-free)
//                  W2 rows  = 176B (176%128=48 -> conflict-free)
#define KS  144
#define HS  176

// ---------------- smem layout (bytes)
#define OFF_K   0                       // [128][72]h  18432
#define OFF_MHI 18432                   // [80][72]h   11520
#define OFF_MLO 29952                   // [80][72]h   11520
#define OFF_W2  41472                   // [40][88]h    7040
#define OFF_C   48512                   // f32[80]
#define OFF_B2  48832                   // f32[40]
#define OFF_WD  48992                   // f32[40]
#define OFF_Q   49152                   // f32[64]
#define OFF_SC  49408                   // f32[128]
#define OFF_SP  49920                   // f32[8*64]
#define OFF_BD  51968
#define SMEM_TOTAL 52096                // x3 CTAs = 156KB <= 228KB/SM

__device__ __forceinline__ unsigned smem_u32(const void* p) {
    unsigned a; asm("{ .reg .u64 t; cvta.to.shared.u64 t, %1; cvt.u32.u64 %0, t; }" : "=r"(a) : "l"(p));
    return a;
}
__device__ __forceinline__ void ldmx4(unsigned a[4], unsigned addr) {
    asm volatile("ldmatrix.sync.aligned.m8n8.x4.shared.b16 {%0,%1,%2,%3}, [%4];"
                 : "=r"(a[0]), "=r"(a[1]), "=r"(a[2]), "=r"(a[3]) : "r"(addr));
}
__device__ __forceinline__ void ldmx2(unsigned a[2], unsigned addr) {
    asm volatile("ldmatrix.sync.aligned.m8n8.x2.shared.b16 {%0,%1}, [%2];"
                 : "=r"(a[0]), "=r"(a[1]) : "r"(addr));
}
__device__ __forceinline__ void mma16816(float d[4], const unsigned a[4], const unsigned b[2]) {
    asm volatile("mma.sync.aligned.m16n8k16.row.col.f32.f16.f16.f32 "
                 "{%0,%1,%2,%3},{%4,%5,%6,%7},{%8,%9},{%0,%1,%2,%3};"
                 : "+f"(d[0]), "+f"(d[1]), "+f"(d[2]), "+f"(d[3])
                 : "r"(a[0]), "r"(a[1]), "r"(a[2]), "r"(a[3]), "r"(b[0]), "r"(b[1]));
}
__device__ __forceinline__ float sigf(float x) { return __fdividef(1.f, 1.f + __expf(-x)); }

// ---------------- device scratch
__device__ float    g_Wkt[H1_ * E_];   // (W1b - W1c)^T [h][e]
__device__ float    g_Wpt[H1_ * E_];   // W1d^T        [h][e]
__device__ float    g_Wqt[H1_ * E_];   // (W1a + W1c)^T[h][e]
__device__ unsigned g_W2h[1760];       // W2^T fp16 image [40 rows j][88 cols h], u32 words
__device__ int      g_len[B_];

// ---------------------------------------------------------------------------
__global__ void prep(const float* __restrict__ W1, const float* __restrict__ W2,
                     const int* __restrict__ raw) {
    int blk = blockIdx.x, tid = threadIdx.x;
    if (blk < 20) {                                   // W1 folds, transposed
        int idx = blk * 256 + tid;
        if (idx >= H1_ * E_) return;
        int h = idx >> 6, e = idx & 63;
        float wa = W1[(e         ) * H1_ + h];
        float wb = W1[(E_     + e) * H1_ + h];
        float wc = W1[(2 * E_ + e) * H1_ + h];
        float wd = W1[(3 * E_ + e) * H1_ + h];
        g_Wqt[idx] = wa + wc;
        g_Wkt[idx] = wb - wc;
        g_Wpt[idx] = wd;
    } else if (blk == 20) {                           // keys_length dtype sniff + clamp
        int any = 0;
        for (int i = 2 * tid + 1; i < B_; i += 512) any |= raw[i];
        int has_odd = __syncthreads_or(any);
        int is64 = (has_odd == 0);
        for (int i = tid; i < B_; i += 256) {
            int v = is64 ? raw[2 * i] : raw[i];
            g_len[i] = v < 0 ? 0 : (v > T_ ? T_ : v);
        }
    } else {                                          // W2^T fp16 image
        int idx = (blk - 21) * 256 + tid;
        if (idx < 1760) {
            int j = idx / 44, w = idx - j * 44;
            int h0 = 2 * w;
            float v0 = (h0     < H1_) ? W2[h0 * H2_ + j]       : 0.f;
            float v1 = (h0 + 1 < H1_) ? W2[(h0 + 1) * H2_ + j] : 0.f;
            __half2 p = __floats2half2_rn(v0, v1);
            g_W2h[idx] = *(unsigned*)&p;
        }
    }
}

// ---------------------------------------------------------------------------
extern __shared__ char smem[];

__global__ void __launch_bounds__(NT, 3)
din_mma(const float* __restrict__ query, const float* __restrict__ keys,
        const float* __restrict__ b1v,   const float* __restrict__ b2v,
        const float* __restrict__ Wdv,   const float* __restrict__ bdv,
        float* __restrict__ out)
{
    const int tid  = threadIdx.x;
    const int wid  = tid >> 5;
    const int lane = tid & 31;
    const int b    = blockIdx.x;
    const int len  = g_len[b];
    const unsigned sb = smem_u32(smem);

    // fragment lane constants
    const int g     = lane >> 2;
    const int t2    = (lane & 3) * 2;
    const int arow  = (lane & 7) + ((lane >> 3) & 1) * 8;
    const int acolB = ((lane >> 4) * 8) * 2;
    const int brow  = lane & 7;
    const int bcolB = ((lane >> 3) & 1) * 16;

    float* sQ  = (float*)(smem + OFF_Q);
    float* sC  = (float*)(smem + OFF_C);
    float* sB2 = (float*)(smem + OFF_B2);
    float* sWd = (float*)(smem + OFF_WD);
    float* sSc = (float*)(smem + OFF_SC);
    float* sSp = (float*)(smem + OFF_SP);

    // ---- phase 0: small vectors
    if (tid < E_) sQ[tid] = query[b * E_ + tid];
    if (tid >= 64 && tid < 64 + H2_) { int j = tid - 64; sB2[j] = b2v[j]; sWd[j] = Wdv[j]; }
    if (tid == 104) *(float*)(smem + OFF_BD) = bdv[0];
    __syncthreads();

    // ---- phase 1: M hi/lo, C, W2 copy
    for (int idx = tid; idx < H1_ * E_; idx += NT) {
        int h = idx >> 6, e = idx & 63;
        float v = g_Wkt[idx] + sQ[e] * g_Wpt[idx];
        __half hi = __float2half_rn(v);
        __half lo = __float2half_rn(v - __half2float(hi));
        *(__half*)(smem + OFF_MHI + h * KS + e * 2) = hi;
        *(__half*)(smem + OFF_MLO + h * KS + e * 2) = lo;
    }
    if (tid < H1_) {
        const float4* wq = (const float4*)&g_Wqt[tid * E_];
        const float4* q4 = (const float4*)sQ;
        float c = b1v[tid];
        #pragma unroll
        for (int i = 0; i < 16; i++) {
            float4 w = wq[i], q = q4[i];
            c += w.x * q.x + w.y * q.y + w.z * q.z + w.w * q.w;
        }
        sC[tid] = c;
    }
    for (int i = tid; i < 1760; i += NT) ((unsigned*)(smem + OFF_W2))[i] = g_W2h[i];
    __syncthreads();

    const float bd = *(float*)(smem + OFF_BD);
    float acc0 = 0.f, acc1 = 0.f;          // pooling accumulators (e = 2*lane, 2*lane+1)

    // per-lane combined ldmatrix.x4 bases:
    //  - M: lanes 0-15 -> Mhi (matrices 0,1 = k0-7 / k8-15), lanes 16-31 -> Mlo (matrices 2,3)
    //  - W2: lanes 0-15 -> n-tile p*2, lanes 16-31 -> n-tile p*2+1
    const unsigned bComb = sb + OFF_MHI + ((lane & 16) ? (OFF_MLO - OFF_MHI) : 0u)
                         + (unsigned)brow * KS + bcolB;
    const unsigned wComb = sb + OFF_W2 + ((lane & 16) ? 8u * HS : 0u)
                         + (unsigned)brow * HS + bcolB;
    const unsigned w4Base = sb + OFF_W2 + (unsigned)(4 * 8 + brow) * HS + bcolB;

    for (int hh = 0; hh < 2; hh++) {
        int hlen = len - HALF * hh;
        if (hlen > HALF) hlen = HALF;
        if (hlen <= 0) break;
        const int mt = (hlen + 15) >> 4;   // m16 tiles this half (<=8)

        // ---- convert K half: fp32 -> fp16; zero only rows [hlen, mt*16)
        {
            int zcnt = (mt * 16 - hlen) * (KS / 4);
            unsigned* zh = (unsigned*)(smem + OFF_K + hlen * KS);
            for (int i = tid; i < zcnt; i += NT) zh[i] = 0;
            const float4* kb = (const float4*)(keys + (size_t)b * (T_ * E_) + HALF * hh * E_);
            int n4 = hlen * 16;
            for (int i4 = tid; i4 < n4; i4 += NT) {
                float4 v = kb[i4];
                int tl = i4 >> 4, e4 = (i4 & 15) << 2;
                __half2 h0 = __floats2half2_rn(v.x, v.y);
                __half2 h1 = __floats2half2_rn(v.z, v.w);
                *(uint2*)(smem + OFF_K + (unsigned)tl * KS + (unsigned)e4 * 2) =
                    make_uint2(*(unsigned*)&h0, *(unsigned*)&h1);
            }
        }
        __syncthreads();

        // ---- fused layer1+layer2: warp w owns m-tile w through both layers.
        if (wid < mt) {
            unsigned Ah[4][4];
            unsigned aB = sb + OFF_K + (unsigned)(wid * 16 + arow) * KS + acolB;
            #pragma unroll
            for (int kt = 0; kt < 4; kt++) ldmx4(Ah[kt], aB + kt * 32);

            float D2[5][4];
            #pragma unroll
            for (int n = 0; n < 5; n++)
                #pragma unroll
                for (int r = 0; r < 4; r++) D2[n][r] = 0.f;

            #pragma unroll
            for (int kc = 0; kc < 5; kc++) {           // k-chunk = nt pair (2kc, 2kc+1)
                float De[4] = {0.f,0.f,0.f,0.f};
                float Do[4] = {0.f,0.f,0.f,0.f};
                unsigned bE = bComb + (unsigned)(kc * 16) * KS;
                unsigned bO = bE + 8u * KS;
                #pragma unroll
                for (int kt = 0; kt < 4; kt++) {
                    unsigned Be[4], Bo[4];             // r0,r1 = Bhi; r2,r3 = Blo
                    ldmx4(Be, bE + kt * 32);
                    ldmx4(Bo, bO + kt * 32);
                    mma16816(De, Ah[kt], Be);
                    mma16816(Do, Ah[kt], Bo);
                    mma16816(De, Ah[kt], Be + 2);
                    mma16816(Do, Ah[kt], Bo + 2);
                }
                // epilogue -> A2 fragment (rows g/g+8, k16 chunk kc of layer-2)
                int ce = kc * 16 + t2;
                float c0 = sC[ce], c1 = sC[ce + 1], c2 = sC[ce + 8], c3 = sC[ce + 9];
                __half2 a0 = __floats2half2_rn(sigf(De[0] + c0), sigf(De[1] + c1));
                __half2 a1 = __floats2half2_rn(sigf(De[2] + c0), sigf(De[3] + c1));
                __half2 a2 = __floats2half2_rn(sigf(Do[0] + c2), sigf(Do[1] + c3));
                __half2 a3 = __floats2half2_rn(sigf(Do[2] + c2), sigf(Do[3] + c3));
                unsigned A2[4] = { *(unsigned*)&a0, *(unsigned*)&a1,
                                   *(unsigned*)&a2, *(unsigned*)&a3 };
                // W2 fragments: two n-tile pairs via x4, last n-tile via x2
                unsigned Bw01[4], Bw23[4], Bw4[2];
                ldmx4(Bw01, wComb + (unsigned)(kc * 32));
                ldmx4(Bw23, wComb + 16u * HS + (unsigned)(kc * 32));
                ldmx2(Bw4,  w4Base + (unsigned)(kc * 32));
                mma16816(D2[0], A2, Bw01);
                mma16816(D2[1], A2, Bw01 + 2);
                mma16816(D2[2], A2, Bw23);
                mma16816(D2[3], A2, Bw23 + 2);
                mma16816(D2[4], A2, Bw4);
            }

            // ---- scores: sigmoid(D2 + b2) . Wd, reduce over n within lane quad
            float p0 = 0.f, p1 = 0.f;
            #pragma unroll
            for (int n = 0; n < 5; n++) {
                int j0 = n * 8 + t2;
                float w0 = sWd[j0], w1 = sWd[j0 + 1];
                float bb0 = sB2[j0], bb1 = sB2[j0 + 1];
                p0 += sigf(D2[n][0] + bb0) * w0 + sigf(D2[n][1] + bb1) * w1;
                p1 += sigf(D2[n][2] + bb0) * w0 + sigf(D2[n][3] + bb1) * w1;
            }
            p0 += __shfl_xor_sync(0xFFFFFFFFu, p0, 1);
            p0 += __shfl_xor_sync(0xFFFFFFFFu, p0, 2);
            p1 += __shfl_xor_sync(0xFFFFFFFFu, p1, 1);
            p1 += __shfl_xor_sync(0xFFFFFFFFu, p1, 2);
            if ((lane & 3) == 0) {
                sSc[wid * 16 + g]     = p0 + bd;
                sSc[wid * 16 + g + 8] = p1 + bd;
            }
        }
        __syncthreads();

        // ---- pooling: out[e] += sum_{t<hlen} score[t] * keys[t][e]  (exact fp32, L2-hot)
        {
            const float* kb2 = keys + (size_t)b * (T_ * E_) + HALF * hh * E_;
            for (int t = wid; t < hlen; t += 8) {
                float sv = sSc[t];
                float2 kv = *(const float2*)(kb2 + (size_t)t * E_ + 2 * lane);
                acc0 += sv * kv.x;
                acc1 += sv * kv.y;
            }
        }
        // no barrier needed: next phase writes only K (not read here), and the
        // next sSc write is behind the post-convert barrier.
    }

    // ---- final reduce across warps
    sSp[wid * 64 + 2 * lane]     = acc0;
    sSp[wid * 64 + 2 * lane + 1] = acc1;
    __syncthreads();
    if (tid < E_) {
        float o = 0.f;
        #pragma unroll
        for (int w = 0; w < 8; w++) o += sSp[w * 64 + tid];
        out[b * E_ + tid] = o;
    }
}

// ---------------------------------------------------------------------------
extern "C" void kernel_launch(void* const* d_in, const int* in_sizes, int n_in,
                              void* d_out, int out_size) {
    const float* query = (const float*)d_in[0];
    const float* keys  = (const float*)d_in[1];
    const int*   klen  = (const int*)  d_in[2];
    const float* W1    = (const float*)d_in[3];
    const float* b1    = (const float*)d_in[4];
    const float* W2    = (const float*)d_in[5];
    const float* b2    = (const float*)d_in[6];
    const float* Wd    = (const float*)d_in[7];
    const float* bd    = (const float*)d_in[8];
    float* out = (float*)d_out;

    cudaFuncSetAttribute(din_mma, cudaFuncAttributeMaxDynamicSharedMemorySize, SMEM_TOTAL);

    prep<<<28, 256>>>(W1, W2, klen);
    din_mma<<<B_, NT, SMEM_TOTAL>>>(query, keys, b1, b2, Wd, bd, out);
}